// round 4
// baseline (speedup 1.0000x reference)
#include <cuda_runtime.h>
#include <cstdint>

#define HIDDEN 1024
#define HEADS  16
#define DKH    64
#define BB     2
#define NN     2048
#define ROWS   (BB*NN)   // 4096

// Static scratch (no allocation allowed)
__device__ float g_Q[ROWS * HIDDEN];
__device__ float g_K[ROWS * HIDDEN];
__device__ float g_V[ROWS * HIDDEN];
__device__ float g_C[ROWS * HIDDEN];
__device__ float g_BM[(size_t)BB * NN * NN];   // bias + mask, 33.5 MB

// ---------------------------------------------------------------------------
// TF32 helpers
// ---------------------------------------------------------------------------
__device__ __forceinline__ uint32_t f2tf(float x) {
    uint32_t u;
    asm("cvt.rna.tf32.f32 %0, %1;" : "=r"(u) : "f"(x));
    return u;
}
__device__ __forceinline__ uint2 split2(float x) {
    uint32_t hi = f2tf(x);
    uint32_t lo = f2tf(x - __uint_as_float(hi));
    return make_uint2(hi, lo);
}
// D(16x8) += A(16x8 tf32) * B(8x8 tf32), row.col
__device__ __forceinline__ void mma8(float* d,
    uint32_t a0, uint32_t a1, uint32_t a2, uint32_t a3,
    uint32_t b0, uint32_t b1)
{
    asm volatile(
        "mma.sync.aligned.m16n8k8.row.col.f32.tf32.tf32.f32 "
        "{%0,%1,%2,%3},{%4,%5,%6,%7},{%8,%9},{%0,%1,%2,%3};"
        : "+f"(d[0]), "+f"(d[1]), "+f"(d[2]), "+f"(d[3])
        : "r"(a0), "r"(a1), "r"(a2), "r"(a3), "r"(b0), "r"(b1));
}

// ---------------------------------------------------------------------------
// bm = bias + mask (one pass, 8M floats)
// ---------------------------------------------------------------------------
__global__ void add_bm_kernel(const float* __restrict__ a,
                              const float* __restrict__ m,
                              float* __restrict__ o, int n4)
{
    int i = blockIdx.x * blockDim.x + threadIdx.x;
    if (i < n4) {
        float4 x = ((const float4*)a)[i];
        float4 y = ((const float4*)m)[i];
        x.x += y.x; x.y += y.y; x.z += y.z; x.w += y.w;
        ((float4*)o)[i] = x;
    }
}

// ---------------------------------------------------------------------------
// 3xTF32 GEMM: C[M,N] = A[M,K] @ W[K,N] + bias
// BM=128 BN=128 BK=16, 256 thr = 8 warps (4m x 2n), warp tile 32x64.
// smem tiles hold (hi,lo) uint2. Reg-double-buffered global loads.
// ---------------------------------------------------------------------------
__global__ void __launch_bounds__(256) gemm3t_kernel(
    const float* __restrict__ A, const float* __restrict__ W,
    const float* __restrict__ bias, float* __restrict__ C,
    int M, int N, int K)
{
    __shared__ uint2 As[16][132];   // [k][m] transposed
    __shared__ uint2 Bs[16][132];   // [k][n]

    const int tid  = threadIdx.x;
    const int lane = tid & 31, wid = tid >> 5;
    const int g = lane >> 2, t = lane & 3;
    const int wm = (wid & 3) * 32;
    const int wn = (wid >> 2) * 64;
    const int bm = blockIdx.y, bn = blockIdx.x;

    const float* Ab = A + (size_t)bm * 128 * K;
    const float* Wb = W + (size_t)bn * 128;

    float acc[2][8][4];
#pragma unroll
    for (int mi = 0; mi < 2; mi++)
#pragma unroll
        for (int n = 0; n < 8; n++)
#pragma unroll
            for (int j = 0; j < 4; j++) acc[mi][n][j] = 0.f;

    int arow[2], ac4[2], wrw[2], wc4[2];
#pragma unroll
    for (int ld = 0; ld < 2; ld++) {
        int li = tid + ld * 256;
        arow[ld] = li >> 2;  ac4[ld] = li & 3;
        wrw[ld]  = li >> 5;  wc4[ld] = li & 31;
    }

    float4 ra[2], rw[2];
#pragma unroll
    for (int ld = 0; ld < 2; ld++) {
        ra[ld] = *(const float4*)(Ab + (size_t)arow[ld] * K + ac4[ld] * 4);
        rw[ld] = *(const float4*)(Wb + (size_t)wrw[ld] * N + wc4[ld] * 4);
    }

    for (int k0 = 0; k0 < K; k0 += 16) {
        // store prefetched tile (split hi/lo)
#pragma unroll
        for (int ld = 0; ld < 2; ld++) {
            int r = arow[ld], c = ac4[ld];
            As[c * 4 + 0][r] = split2(ra[ld].x);
            As[c * 4 + 1][r] = split2(ra[ld].y);
            As[c * 4 + 2][r] = split2(ra[ld].z);
            As[c * 4 + 3][r] = split2(ra[ld].w);
            int kr = wrw[ld], cc = wc4[ld] * 4;
            Bs[kr][cc + 0] = split2(rw[ld].x);
            Bs[kr][cc + 1] = split2(rw[ld].y);
            Bs[kr][cc + 2] = split2(rw[ld].z);
            Bs[kr][cc + 3] = split2(rw[ld].w);
        }
        __syncthreads();

        if (k0 + 16 < K) {
#pragma unroll
            for (int ld = 0; ld < 2; ld++) {
                ra[ld] = *(const float4*)(Ab + (size_t)arow[ld] * K + (k0 + 16) + ac4[ld] * 4);
                rw[ld] = *(const float4*)(Wb + (size_t)(k0 + 16 + wrw[ld]) * N + wc4[ld] * 4);
            }
        }

#pragma unroll
        for (int ks = 0; ks < 2; ks++) {
            uint2 Af[2][4];
#pragma unroll
            for (int mi = 0; mi < 2; mi++) {
                Af[mi][0] = As[ks * 8 + t]    [wm + mi * 16 + g];
                Af[mi][1] = As[ks * 8 + t]    [wm + mi * 16 + g + 8];
                Af[mi][2] = As[ks * 8 + t + 4][wm + mi * 16 + g];
                Af[mi][3] = As[ks * 8 + t + 4][wm + mi * 16 + g + 8];
            }
#pragma unroll
            for (int n = 0; n < 8; n++) {
                uint2 B0 = Bs[ks * 8 + t]    [wn + n * 8 + g];
                uint2 B1 = Bs[ks * 8 + t + 4][wn + n * 8 + g];
#pragma unroll
                for (int mi = 0; mi < 2; mi++) {
                    mma8(acc[mi][n], Af[mi][0].x, Af[mi][1].x, Af[mi][2].x, Af[mi][3].x, B0.x, B1.x);
                    mma8(acc[mi][n], Af[mi][0].y, Af[mi][1].y, Af[mi][2].y, Af[mi][3].y, B0.x, B1.x);
                    mma8(acc[mi][n], Af[mi][0].x, Af[mi][1].x, Af[mi][2].x, Af[mi][3].x, B0.y, B1.y);
                }
            }
        }
        __syncthreads();
    }

    // epilogue
#pragma unroll
    for (int mi = 0; mi < 2; mi++) {
        int row0 = bm * 128 + wm + mi * 16 + g;
#pragma unroll
        for (int n = 0; n < 8; n++) {
            int col = bn * 128 + wn + n * 8 + 2 * t;
            float2 bv = *(const float2*)(bias + col);
            float2 o0, o1;
            o0.x = acc[mi][n][0] + bv.x;  o0.y = acc[mi][n][1] + bv.y;
            o1.x = acc[mi][n][2] + bv.x;  o1.y = acc[mi][n][3] + bv.y;
            *(float2*)(C + (size_t)row0 * N + col)       = o0;
            *(float2*)(C + (size_t)(row0 + 8) * N + col) = o1;
        }
    }
}

// ---------------------------------------------------------------------------
// Flash attention, tensor-core. Br=64, Bc=64, Dk=64. 128 thr = 4 warps,
// each warp owns 16 q-rows. QK^T 1xTF32 (Q frags in regs), PV 3xTF32.
// smem: Kt u32[64][72] (tf32 K^T, also Q staging), Vs uint2[64][72],
//       Ps f32[4][16][68]  => 72704 B dynamic.
// ---------------------------------------------------------------------------
#define FSM_BYTES (18432 + 36864 + 17408)

__global__ void __launch_bounds__(128) flash_kernel(float* __restrict__ ctx)
{
    extern __shared__ char sm[];
    uint32_t* Kt = (uint32_t*)sm;                 // [64][72] tf32
    float*    Qs = (float*)sm;                    // staging alias [64][72]
    uint2*    Vs = (uint2*)(sm + 18432);          // [64][72] (hi,lo)
    float*    Ps = (float*)(sm + 18432 + 36864);  // [4][16][68]

    const int tid  = threadIdx.x;
    const int lane = tid & 31, wid = tid >> 5;
    const int g = lane >> 2, t = lane & 3;
    const int wrow = wid * 16;

    const int h  = blockIdx.x;
    const int q0 = blockIdx.y * 64;
    const int b  = blockIdx.z;

    const float* Qg = g_Q + ((size_t)b * NN + q0) * HIDDEN + h * DKH;
    const float* Kg = g_K + (size_t)b * NN * HIDDEN + h * DKH;
    const float* Vg = g_V + (size_t)b * NN * HIDDEN + h * DKH;

    // ---- stage Q, build Q fragments (scale folded: 2^-3, exact) ----
#pragma unroll
    for (int i = 0; i < 8; i++) {
        int li = tid + i * 128;          // 0..1023
        int r  = li >> 4, c4 = li & 15;
        *(float4*)&Qs[r * 72 + c4 * 4] =
            *(const float4*)(Qg + (size_t)r * HIDDEN + c4 * 4);
    }
    __syncthreads();

    uint32_t qa[8][4];
#pragma unroll
    for (int kb = 0; kb < 8; kb++) {
        qa[kb][0] = f2tf(Qs[(wrow + g)     * 72 + kb * 8 + t]     * 0.125f);
        qa[kb][1] = f2tf(Qs[(wrow + g + 8) * 72 + kb * 8 + t]     * 0.125f);
        qa[kb][2] = f2tf(Qs[(wrow + g)     * 72 + kb * 8 + t + 4] * 0.125f);
        qa[kb][3] = f2tf(Qs[(wrow + g + 8) * 72 + kb * 8 + t + 4] * 0.125f);
    }

    float Oa[8][4];
#pragma unroll
    for (int n = 0; n < 8; n++)
#pragma unroll
        for (int j = 0; j < 4; j++) Oa[n][j] = 0.f;
    float m0 = -1e30f, m1 = -1e30f, l0 = 0.f, l1 = 0.f;

    const float* bmBase = g_BM + ((size_t)b * NN + q0 + wrow) * NN;
    float* pr0 = Ps + (wid * 16 + g) * 68;
    float* pr1 = pr0 + 8 * 68;

    for (int kt = 0; kt < NN / 64; kt++) {
        const int k0 = kt * 64;
        __syncthreads();   // previous tile (or Q-frag build) fully consumed

        // ---- load K (transposed tf32) and V (hi/lo) ----
#pragma unroll
        for (int i = 0; i < 8; i++) {
            int li = tid + i * 128;
            int r  = li >> 4, c4 = li & 15;
            float4 kv = *(const float4*)(Kg + (size_t)(k0 + r) * HIDDEN + c4 * 4);
            Kt[(c4 * 4 + 0) * 72 + r] = f2tf(kv.x);
            Kt[(c4 * 4 + 1) * 72 + r] = f2tf(kv.y);
            Kt[(c4 * 4 + 2) * 72 + r] = f2tf(kv.z);
            Kt[(c4 * 4 + 3) * 72 + r] = f2tf(kv.w);
            float4 vv = *(const float4*)(Vg + (size_t)(k0 + r) * HIDDEN + c4 * 4);
            Vs[r * 72 + c4 * 4 + 0] = split2(vv.x);
            Vs[r * 72 + c4 * 4 + 1] = split2(vv.y);
            Vs[r * 72 + c4 * 4 + 2] = split2(vv.z);
            Vs[r * 72 + c4 * 4 + 3] = split2(vv.w);
        }
        __syncthreads();

        // ---- S = (Q*scale) @ K^T  (1xTF32) ----
        float sacc[8][4];
#pragma unroll
        for (int n = 0; n < 8; n++)
#pragma unroll
            for (int j = 0; j < 4; j++) sacc[n][j] = 0.f;

#pragma unroll
        for (int kb = 0; kb < 8; kb++) {
#pragma unroll
            for (int n = 0; n < 8; n++) {
                uint32_t b0 = Kt[(kb * 8 + t)     * 72 + n * 8 + g];
                uint32_t b1 = Kt[(kb * 8 + t + 4) * 72 + n * 8 + g];
                mma8(sacc[n], qa[kb][0], qa[kb][1], qa[kb][2], qa[kb][3], b0, b1);
            }
        }

        // ---- + (bias+mask), online softmax ----
        const float* bm0 = bmBase + (size_t)g * NN + k0;
        const float* bm1 = bmBase + (size_t)(g + 8) * NN + k0;
        float mx0 = -1e30f, mx1 = -1e30f;
#pragma unroll
        for (int n = 0; n < 8; n++) {
            float2 u = *(const float2*)(bm0 + n * 8 + 2 * t);
            float2 w = *(const float2*)(bm1 + n * 8 + 2 * t);
            sacc[n][0] += u.x; sacc[n][1] += u.y;
            sacc[n][2] += w.x; sacc[n][3] += w.y;
            mx0 = fmaxf(mx0, fmaxf(sacc[n][0], sacc[n][1]));
            mx1 = fmaxf(mx1, fmaxf(sacc[n][2], sacc[n][3]));
        }
        mx0 = fmaxf(mx0, __shfl_xor_sync(0xffffffffu, mx0, 1));
        mx0 = fmaxf(mx0, __shfl_xor_sync(0xffffffffu, mx0, 2));
        mx1 = fmaxf(mx1, __shfl_xor_sync(0xffffffffu, mx1, 1));
        mx1 = fmaxf(mx1, __shfl_xor_sync(0xffffffffu, mx1, 2));

        float mn0 = fmaxf(m0, mx0), mn1 = fmaxf(m1, mx1);
        float c0 = __expf(m0 - mn0), c1 = __expf(m1 - mn1);
        float rs0 = 0.f, rs1 = 0.f;
#pragma unroll
        for (int n = 0; n < 8; n++) {
            float p0 = __expf(sacc[n][0] - mn0);
            float p1 = __expf(sacc[n][1] - mn0);
            float p2 = __expf(sacc[n][2] - mn1);
            float p3 = __expf(sacc[n][3] - mn1);
            rs0 += p0 + p1; rs1 += p2 + p3;
            *(float2*)&pr0[n * 8 + 2 * t] = make_float2(p0, p1);
            *(float2*)&pr1[n * 8 + 2 * t] = make_float2(p2, p3);
        }
        rs0 += __shfl_xor_sync(0xffffffffu, rs0, 1);
        rs0 += __shfl_xor_sync(0xffffffffu, rs0, 2);
        rs1 += __shfl_xor_sync(0xffffffffu, rs1, 1);
        rs1 += __shfl_xor_sync(0xffffffffu, rs1, 2);

        l0 = l0 * c0 + rs0;  l1 = l1 * c1 + rs1;
        m0 = mn0;            m1 = mn1;
#pragma unroll
        for (int n = 0; n < 8; n++) {
            Oa[n][0] *= c0; Oa[n][1] *= c0;
            Oa[n][2] *= c1; Oa[n][3] *= c1;
        }
        __syncwarp();

        // ---- O += P @ V  (3xTF32) ----
#pragma unroll
        for (int kb = 0; kb < 8; kb++) {
            uint2 A0 = split2(pr0[kb * 8 + t]);
            uint2 A1 = split2(pr1[kb * 8 + t]);
            uint2 A2 = split2(pr0[kb * 8 + t + 4]);
            uint2 A3 = split2(pr1[kb * 8 + t + 4]);
#pragma unroll
            for (int n = 0; n < 8; n++) {
                uint2 B0 = Vs[(kb * 8 + t)     * 72 + n * 8 + g];
                uint2 B1 = Vs[(kb * 8 + t + 4) * 72 + n * 8 + g];
                mma8(Oa[n], A0.x, A1.x, A2.x, A3.x, B0.x, B1.x);
                mma8(Oa[n], A0.y, A1.y, A2.y, A3.y, B0.x, B1.x);
                mma8(Oa[n], A0.x, A1.x, A2.x, A3.x, B0.y, B1.y);
            }
        }
    }

    // ---- epilogue ----
    float inv0 = 1.f / l0, inv1 = 1.f / l1;
    float* o0 = ctx + ((size_t)b * NN + q0 + wrow + g) * HIDDEN + h * DKH;
    float* o1 = o0 + (size_t)8 * HIDDEN;
#pragma unroll
    for (int n = 0; n < 8; n++) {
        *(float2*)&o0[n * 8 + 2 * t] = make_float2(Oa[n][0] * inv0, Oa[n][1] * inv0);
        *(float2*)&o1[n * 8 + 2 * t] = make_float2(Oa[n][2] * inv1, Oa[n][3] * inv1);
    }
}

// ---------------------------------------------------------------------------
extern "C" void kernel_launch(void* const* d_in, const int* in_sizes, int n_in,
                              void* d_out, int out_size)
{
    const float* q    = (const float*)d_in[0];
    const float* k    = (const float*)d_in[1];
    const float* v    = (const float*)d_in[2];
    const float* abia = (const float*)d_in[3];
    const float* amask= (const float*)d_in[4];
    const float* Wq   = (const float*)d_in[5];
    const float* bq   = (const float*)d_in[6];
    const float* Wk   = (const float*)d_in[7];
    const float* bk   = (const float*)d_in[8];
    const float* Wv   = (const float*)d_in[9];
    const float* bv   = (const float*)d_in[10];
    const float* Wo   = (const float*)d_in[11];
    const float* bo   = (const float*)d_in[12];
    float* out = (float*)d_out;

    float *Qp, *Kp, *Vp, *Cp, *BMp;
    cudaGetSymbolAddress((void**)&Qp, g_Q);
    cudaGetSymbolAddress((void**)&Kp, g_K);
    cudaGetSymbolAddress((void**)&Vp, g_V);
    cudaGetSymbolAddress((void**)&Cp, g_C);
    cudaGetSymbolAddress((void**)&BMp, g_BM);

    cudaFuncSetAttribute(flash_kernel,
                         cudaFuncAttributeMaxDynamicSharedMemorySize, FSM_BYTES);

    int n4 = (int)((size_t)BB * NN * NN / 4);
    add_bm_kernel<<<(n4 + 255) / 256, 256>>>(abia, amask, BMp, n4);

    dim3 gb(HIDDEN / 128, ROWS / 128);   // (8, 32)
    gemm3t_kernel<<<gb, 256>>>(q, Wq, bq, Qp, ROWS, HIDDEN, HIDDEN);
    gemm3t_kernel<<<gb, 256>>>(k, Wk, bk, Kp, ROWS, HIDDEN, HIDDEN);
    gemm3t_kernel<<<gb, 256>>>(v, Wv, bv, Vp, ROWS, HIDDEN, HIDDEN);

    dim3 gf(HEADS, NN / 64, BB);         // heads fastest -> bm tile L2 reuse
    flash_kernel<<<gf, 128, FSM_BYTES>>>(Cp);

    gemm3t_kernel<<<gb, 256>>>(Cp, Wo, bo, out, ROWS, HIDDEN, HIDDEN);
}

// round 5
// speedup vs baseline: 2.4917x; 2.4917x over previous
#include <cuda_runtime.h>
#include <cstdint>

#define HIDDEN 1024
#define HEADS  16
#define DKH    64
#define BB     2
#define NN     2048
#define ROWS   (BB*NN)

__device__ float g_Q[ROWS * HIDDEN];
__device__ float g_K[ROWS * HIDDEN];
__device__ float g_V[ROWS * HIDDEN];
__device__ float g_C[ROWS * HIDDEN];

__device__ __forceinline__ uint32_t f2tf(float x) {
    uint32_t u; asm("cvt.rna.tf32.f32 %0, %1;" : "=r"(u) : "f"(x)); return u;
}
// bf16x2: low half = a, high half = b
__device__ __forceinline__ uint32_t pk(float a, float b) {
    uint32_t r; asm("cvt.rn.bf16x2.f32 %0, %1, %2;" : "=r"(r) : "f"(b), "f"(a)); return r;
}
__device__ __forceinline__ float blo(uint32_t u) { return __uint_as_float(u << 16); }
__device__ __forceinline__ float bhi(uint32_t u) { return __uint_as_float(u & 0xffff0000u); }
// split pair (f0 = even-k, f1 = odd-k) into bf16 hi-pair + residual lo-pair
__device__ __forceinline__ void sp(float f0, float f1, uint32_t& h, uint32_t& l) {
    h = pk(f0, f1);
    l = pk(f0 - blo(h), f1 - bhi(h));
}
__device__ __forceinline__ void mma8(float* d, uint32_t a0, uint32_t a1,
    uint32_t a2, uint32_t a3, uint32_t b0, uint32_t b1) {
    asm volatile("mma.sync.aligned.m16n8k8.row.col.f32.tf32.tf32.f32 "
        "{%0,%1,%2,%3},{%4,%5,%6,%7},{%8,%9},{%0,%1,%2,%3};"
        : "+f"(d[0]), "+f"(d[1]), "+f"(d[2]), "+f"(d[3])
        : "r"(a0), "r"(a1), "r"(a2), "r"(a3), "r"(b0), "r"(b1));
}
__device__ __forceinline__ void mma16(float* d, uint32_t a0, uint32_t a1,
    uint32_t a2, uint32_t a3, uint32_t b0, uint32_t b1) {
    asm volatile("mma.sync.aligned.m16n8k16.row.col.f32.bf16.bf16.f32 "
        "{%0,%1,%2,%3},{%4,%5,%6,%7},{%8,%9},{%0,%1,%2,%3};"
        : "+f"(d[0]), "+f"(d[1]), "+f"(d[2]), "+f"(d[3])
        : "r"(a0), "r"(a1), "r"(a2), "r"(a3), "r"(b0), "r"(b1));
}

// ---------------------------------------------------------------------------
// bf16x3 GEMM: C = A@W + bias. BM=BN=128, BK=16, 8 warps (4m x 2n), 2 CTA/SM.
// Ah/Al: [kpair 8][m 128] bf16x2 pairs along k. Wh/Wl: [kpair 8][n 128].
// ---------------------------------------------------------------------------
__global__ void __launch_bounds__(256, 2) gemm_bf3_kernel(
    const float* __restrict__ A, const float* __restrict__ W,
    const float* __restrict__ bias, float* __restrict__ C,
    int M, int N, int K)
{
    __shared__ uint32_t Ah[8][136], Al[8][136], Wh[8][136], Wl[8][136];
    const int tid = threadIdx.x, lane = tid & 31, wid = tid >> 5;
    const int g = lane >> 2, t = lane & 3;
    const int wm = (wid & 3) * 32, wn = (wid >> 2) * 64;
    const float* Ab = A + (size_t)blockIdx.y * 128 * K;
    const float* Wb = W + (size_t)blockIdx.x * 128;

    float acc[2][8][4];
#pragma unroll
    for (int mi = 0; mi < 2; mi++)
#pragma unroll
        for (int n = 0; n < 8; n++)
#pragma unroll
            for (int j = 0; j < 4; j++) acc[mi][n][j] = 0.f;

    const int arow = tid >> 2, ac4 = tid & 3;   // A: rows arow, arow+64
    const int kp = tid >> 5, c4 = tid & 31;     // W: k-pair kp, cols c4*4..+3

    float4 ra0 = *(const float4*)(Ab + (size_t)arow * K + ac4 * 4);
    float4 ra1 = *(const float4*)(Ab + (size_t)(arow + 64) * K + ac4 * 4);
    float4 rw0 = *(const float4*)(Wb + (size_t)(2 * kp) * N + c4 * 4);
    float4 rw1 = *(const float4*)(Wb + (size_t)(2 * kp + 1) * N + c4 * 4);

    for (int k0 = 0; k0 < K; k0 += 16) {
        uint32_t h, l;
        sp(ra0.x, ra0.y, h, l); Ah[2*ac4][arow] = h;      Al[2*ac4][arow] = l;
        sp(ra0.z, ra0.w, h, l); Ah[2*ac4+1][arow] = h;    Al[2*ac4+1][arow] = l;
        sp(ra1.x, ra1.y, h, l); Ah[2*ac4][arow+64] = h;   Al[2*ac4][arow+64] = l;
        sp(ra1.z, ra1.w, h, l); Ah[2*ac4+1][arow+64] = h; Al[2*ac4+1][arow+64] = l;
        uint4 vh, vl;
        sp(rw0.x, rw1.x, vh.x, vl.x); sp(rw0.y, rw1.y, vh.y, vl.y);
        sp(rw0.z, rw1.z, vh.z, vl.z); sp(rw0.w, rw1.w, vh.w, vl.w);
        *(uint4*)&Wh[kp][c4 * 4] = vh;
        *(uint4*)&Wl[kp][c4 * 4] = vl;
        __syncthreads();

        if (k0 + 16 < K) {
            ra0 = *(const float4*)(Ab + (size_t)arow * K + k0 + 16 + ac4 * 4);
            ra1 = *(const float4*)(Ab + (size_t)(arow + 64) * K + k0 + 16 + ac4 * 4);
            rw0 = *(const float4*)(Wb + (size_t)(k0 + 16 + 2 * kp) * N + c4 * 4);
            rw1 = *(const float4*)(Wb + (size_t)(k0 + 17 + 2 * kp) * N + c4 * 4);
        }

        uint32_t af[2][8];
#pragma unroll
        for (int mi = 0; mi < 2; mi++) {
            int mb = wm + mi * 16;
            af[mi][0] = Ah[t][mb+g];   af[mi][1] = Ah[t][mb+g+8];
            af[mi][2] = Ah[t+4][mb+g]; af[mi][3] = Ah[t+4][mb+g+8];
            af[mi][4] = Al[t][mb+g];   af[mi][5] = Al[t][mb+g+8];
            af[mi][6] = Al[t+4][mb+g]; af[mi][7] = Al[t+4][mb+g+8];
        }
#pragma unroll
        for (int n = 0; n < 8; n++) {
            uint32_t b0h = Wh[t][wn+n*8+g], b1h = Wh[t+4][wn+n*8+g];
            uint32_t b0l = Wl[t][wn+n*8+g], b1l = Wl[t+4][wn+n*8+g];
#pragma unroll
            for (int mi = 0; mi < 2; mi++) {
                mma16(acc[mi][n], af[mi][0], af[mi][1], af[mi][2], af[mi][3], b0h, b1h);
                mma16(acc[mi][n], af[mi][4], af[mi][5], af[mi][6], af[mi][7], b0h, b1h);
                mma16(acc[mi][n], af[mi][0], af[mi][1], af[mi][2], af[mi][3], b0l, b1l);
            }
        }
        __syncthreads();
    }

#pragma unroll
    for (int mi = 0; mi < 2; mi++) {
        int row0 = blockIdx.y * 128 + wm + mi * 16 + g;
#pragma unroll
        for (int n = 0; n < 8; n++) {
            int col = blockIdx.x * 128 + wn + n * 8 + 2 * t;
            float2 bv = *(const float2*)(bias + col);
            *(float2*)(C + (size_t)row0 * N + col) =
                make_float2(acc[mi][n][0] + bv.x, acc[mi][n][1] + bv.y);
            *(float2*)(C + (size_t)(row0 + 8) * N + col) =
                make_float2(acc[mi][n][2] + bv.x, acc[mi][n][3] + bv.y);
        }
    }
}

// ---------------------------------------------------------------------------
// Flash: Br=128, Bc=64, Dk=64. 256 thr = 8 warps, warp w -> q-rows [16w,16w+16).
// QK^T: 1xTF32 m16n8k8 (Q frags in regs, K row-major tf32 in smem).
// PV: bf16x3 m16n8k16, P in registers. V as bf16 hi/lo row-pairs.
// ---------------------------------------------------------------------------
__global__ void __launch_bounds__(256) flash_kernel(
    const float* __restrict__ bias, const float* __restrict__ mask,
    float* __restrict__ ctx)
{
    __shared__ uint32_t Ks[64 * 68];          // [key][dim] tf32
    __shared__ uint32_t Vh[32 * 72], Vl[32 * 72];  // [keypair][dim]

    const int tid = threadIdx.x, lane = tid & 31, wid = tid >> 5;
    const int g = lane >> 2, t = lane & 3;
    const int wrow = wid * 16;
    const int h = blockIdx.x, q0 = blockIdx.y * 128, b = blockIdx.z;

    const float* Qg = g_Q + ((size_t)b * NN + q0) * HIDDEN + h * DKH;
    const float* Kg = g_K + (size_t)b * NN * HIDDEN + h * DKH;
    const float* Vg = g_V + (size_t)b * NN * HIDDEN + h * DKH;

    uint32_t qa[8][4];
#pragma unroll
    for (int kb = 0; kb < 8; kb++) {
        qa[kb][0] = f2tf(__ldg(Qg + (size_t)(wrow+g)  *HIDDEN + kb*8 + t)   * 0.125f);
        qa[kb][1] = f2tf(__ldg(Qg + (size_t)(wrow+g+8)*HIDDEN + kb*8 + t)   * 0.125f);
        qa[kb][2] = f2tf(__ldg(Qg + (size_t)(wrow+g)  *HIDDEN + kb*8 + t+4) * 0.125f);
        qa[kb][3] = f2tf(__ldg(Qg + (size_t)(wrow+g+8)*HIDDEN + kb*8 + t+4) * 0.125f);
    }

    float Oa[8][4];
#pragma unroll
    for (int n = 0; n < 8; n++)
#pragma unroll
        for (int j = 0; j < 4; j++) Oa[n][j] = 0.f;
    float m0 = -1e30f, m1 = -1e30f, l0 = 0.f, l1 = 0.f;

    const float* biasB = bias + ((size_t)b * NN + q0 + wrow) * NN;
    const float* maskB = mask + ((size_t)b * NN + q0 + wrow) * NN;

    for (int kt = 0; kt < NN / 64; kt++) {
        const int k0 = kt * 64;
        __syncthreads();

        // K tile (row-major tf32)
#pragma unroll
        for (int i = 0; i < 4; i++) {
            int li = tid + i * 256, r = li >> 4, cc = li & 15;
            float4 kv = *(const float4*)(Kg + (size_t)(k0 + r) * HIDDEN + cc * 4);
            uint4 u; u.x = f2tf(kv.x); u.y = f2tf(kv.y); u.z = f2tf(kv.z); u.w = f2tf(kv.w);
            *(uint4*)&Ks[r * 68 + cc * 4] = u;
        }
        // V tile (bf16 pairs across key row-pairs)
#pragma unroll
        for (int i = 0; i < 4; i++) {
            int li = tid + i * 256, rp = li >> 5, c2 = li & 31;
            float2 v0 = *(const float2*)(Vg + (size_t)(k0 + 2*rp)   * HIDDEN + c2 * 2);
            float2 v1 = *(const float2*)(Vg + (size_t)(k0 + 2*rp+1) * HIDDEN + c2 * 2);
            uint2 uh, ul;
            sp(v0.x, v1.x, uh.x, ul.x);
            sp(v0.y, v1.y, uh.y, ul.y);
            *(uint2*)&Vh[rp * 72 + c2 * 2] = uh;
            *(uint2*)&Vl[rp * 72 + c2 * 2] = ul;
        }
        __syncthreads();

        // S = (Q/8) @ K^T
        float sacc[8][4];
#pragma unroll
        for (int n = 0; n < 8; n++)
#pragma unroll
            for (int j = 0; j < 4; j++) sacc[n][j] = 0.f;
#pragma unroll
        for (int kb = 0; kb < 8; kb++)
#pragma unroll
            for (int n = 0; n < 8; n++) {
                uint32_t b0 = Ks[(n*8+g) * 68 + kb*8 + t];
                uint32_t b1 = Ks[(n*8+g) * 68 + kb*8 + t + 4];
                mma8(sacc[n], qa[kb][0], qa[kb][1], qa[kb][2], qa[kb][3], b0, b1);
            }

        // + bias + mask, online softmax (rows g, g+8)
        const float* b0p = biasB + (size_t)g * NN + k0;
        const float* b1p = biasB + (size_t)(g+8) * NN + k0;
        const float* m0p = maskB + (size_t)g * NN + k0;
        const float* m1p = maskB + (size_t)(g+8) * NN + k0;
        float mx0 = -1e30f, mx1 = -1e30f;
#pragma unroll
        for (int n = 0; n < 8; n++) {
            float2 u  = __ldg((const float2*)(b0p + n*8 + 2*t));
            float2 um = __ldg((const float2*)(m0p + n*8 + 2*t));
            float2 w  = __ldg((const float2*)(b1p + n*8 + 2*t));
            float2 wm = __ldg((const float2*)(m1p + n*8 + 2*t));
            sacc[n][0] += u.x + um.x; sacc[n][1] += u.y + um.y;
            sacc[n][2] += w.x + wm.x; sacc[n][3] += w.y + wm.y;
            mx0 = fmaxf(mx0, fmaxf(sacc[n][0], sacc[n][1]));
            mx1 = fmaxf(mx1, fmaxf(sacc[n][2], sacc[n][3]));
        }
        mx0 = fmaxf(mx0, __shfl_xor_sync(~0u, mx0, 1));
        mx0 = fmaxf(mx0, __shfl_xor_sync(~0u, mx0, 2));
        mx1 = fmaxf(mx1, __shfl_xor_sync(~0u, mx1, 1));
        mx1 = fmaxf(mx1, __shfl_xor_sync(~0u, mx1, 2));
        float mn0 = fmaxf(m0, mx0), mn1 = fmaxf(m1, mx1);
        float c0 = __expf(m0 - mn0), c1 = __expf(m1 - mn1);
        float rs0 = 0.f, rs1 = 0.f;
#pragma unroll
        for (int n = 0; n < 8; n++) {
            sacc[n][0] = __expf(sacc[n][0] - mn0);
            sacc[n][1] = __expf(sacc[n][1] - mn0);
            sacc[n][2] = __expf(sacc[n][2] - mn1);
            sacc[n][3] = __expf(sacc[n][3] - mn1);
            rs0 += sacc[n][0] + sacc[n][1];
            rs1 += sacc[n][2] + sacc[n][3];
        }
        rs0 += __shfl_xor_sync(~0u, rs0, 1); rs0 += __shfl_xor_sync(~0u, rs0, 2);
        rs1 += __shfl_xor_sync(~0u, rs1, 1); rs1 += __shfl_xor_sync(~0u, rs1, 2);
        l0 = l0 * c0 + rs0; l1 = l1 * c1 + rs1;
        m0 = mn0; m1 = mn1;
#pragma unroll
        for (int n = 0; n < 8; n++) {
            Oa[n][0] *= c0; Oa[n][1] *= c0;
            Oa[n][2] *= c1; Oa[n][3] *= c1;
        }

        // O += P @ V (bf16x3: Ph*Vh + Pl*Vh + Ph*Vl), P in regs
#pragma unroll
        for (int kb = 0; kb < 4; kb++) {
            uint32_t a0h, a0l, a1h, a1l, a2h, a2l, a3h, a3l;
            sp(sacc[2*kb][0],   sacc[2*kb][1],   a0h, a0l);
            sp(sacc[2*kb][2],   sacc[2*kb][3],   a1h, a1l);
            sp(sacc[2*kb+1][0], sacc[2*kb+1][1], a2h, a2l);
            sp(sacc[2*kb+1][2], sacc[2*kb+1][3], a3h, a3l);
#pragma unroll
            for (int n = 0; n < 8; n++) {
                uint32_t b0h = Vh[(kb*8+t)   * 72 + n*8 + g];
                uint32_t b1h = Vh[(kb*8+t+4) * 72 + n*8 + g];
                uint32_t b0l = Vl[(kb*8+t)   * 72 + n*8 + g];
                uint32_t b1l = Vl[(kb*8+t+4) * 72 + n*8 + g];
                mma16(Oa[n], a0h, a1h, a2h, a3h, b0h, b1h);
                mma16(Oa[n], a0l, a1l, a2l, a3l, b0h, b1h);
                mma16(Oa[n], a0h, a1h, a2h, a3h, b0l, b1l);
            }
        }
    }

    float inv0 = 1.f / l0, inv1 = 1.f / l1;
    float* o0 = ctx + ((size_t)b * NN + q0 + wrow + g) * HIDDEN + h * DKH;
    float* o1 = o0 + (size_t)8 * HIDDEN;
#pragma unroll
    for (int n = 0; n < 8; n++) {
        *(float2*)&o0[n*8 + 2*t] = make_float2(Oa[n][0]*inv0, Oa[n][1]*inv0);
        *(float2*)&o1[n*8 + 2*t] = make_float2(Oa[n][2]*inv1, Oa[n][3]*inv1);
    }
}

extern "C" void kernel_launch(void* const* d_in, const int* in_sizes, int n_in,
                              void* d_out, int out_size)
{
    const float* q    = (const float*)d_in[0];
    const float* k    = (const float*)d_in[1];
    const float* v    = (const float*)d_in[2];
    const float* abia = (const float*)d_in[3];
    const float* amask= (const float*)d_in[4];
    const float* Wq   = (const float*)d_in[5];
    const float* bq   = (const float*)d_in[6];
    const float* Wk   = (const float*)d_in[7];
    const float* bk   = (const float*)d_in[8];
    const float* Wv   = (const float*)d_in[9];
    const float* bv   = (const float*)d_in[10];
    const float* Wo   = (const float*)d_in[11];
    const float* bo   = (const float*)d_in[12];
    float* out = (float*)d_out;

    float *Qp, *Kp, *Vp, *Cp;
    cudaGetSymbolAddress((void**)&Qp, g_Q);
    cudaGetSymbolAddress((void**)&Kp, g_K);
    cudaGetSymbolAddress((void**)&Vp, g_V);
    cudaGetSymbolAddress((void**)&Cp, g_C);

    dim3 gb(HIDDEN / 128, ROWS / 128);     // (8, 32)
    gemm_bf3_kernel<<<gb, 256>>>(q, Wq, bq, Qp, ROWS, HIDDEN, HIDDEN);
    gemm_bf3_kernel<<<gb, 256>>>(k, Wk, bk, Kp, ROWS, HIDDEN, HIDDEN);
    gemm_bf3_kernel<<<gb, 256>>>(v, Wv, bv, Vp, ROWS, HIDDEN, HIDDEN);

    dim3 gf(HEADS, NN / 128, BB);          // (16, 16, 2)
    flash_kernel<<<gf, 256>>>(abia, amask, Cp);

    gemm_bf3_kernel<<<gb, 256>>>(Cp, Wo, bo, out, ROWS, HIDDEN, HIDDEN);
}